// round 4
// baseline (speedup 1.0000x reference)
#include <cuda_runtime.h>
#include <math.h>

#define B_    4
#define CIN_  3
#define HALF_ 32
#define HW_   512
#define PLANE_ 262144   // 512*512
#define NBIN_ 4913      // 17^3

// ---------------- scratch (device globals: allocation-free) ----------------
__device__ __align__(128) unsigned char  g_kmode[B_ * CIN_ * PLANE_];   // 3 MB
__device__ __align__(128) unsigned short g_bin[B_ * PLANE_];            // 2 MB
__device__ unsigned int g_hist[NBIN_];
__device__ __align__(128) float g_htab[NBIN_ * 32];                     // 629 KB
__device__ float g_d1[B_ * HALF_ * 171 * 171];
__device__ float g_d2[B_ * HALF_ * 57 * 57];
__device__ float g_d3[B_ * HALF_ * 19 * 19];
__device__ float g_d4[B_ * HALF_ * 7 * 7];
__device__ float g_d5[B_ * HALF_ * 3 * 3];
__device__ float g_d6[B_ * HALF_ * 1 * 1];
__device__ float g_scale1[32], g_bias1[32], g_scale2[32], g_bias2[32];
__device__ float g_cA[6 * 64], g_cB[6 * 64];

__device__ __forceinline__ float leaky(float v) { return fmaxf(v, 0.01f * v); }

// ---------------- 0: zero the histogram (graph-replay safe) ----------------
__global__ void zero_hist_kernel() {
    for (int i = threadIdx.x; i < NBIN_; i += 1024) g_hist[i] = 0;
}

// ---------------- 1: mode pooling (quantize + 11x11 window mode) -----------
// Column-strip sliding histogram: 17 levels packed as bytes in 5 u32 words.
// grid (64 row-blocks, 4 col-strips, 12 images), 128 threads.
#define MROWS 8
__global__ __launch_bounds__(128) void mode_kernel(const float* __restrict__ x) {
    __shared__ unsigned int hist[138 * 5];
    const int bc = blockIdx.z;
    const int cs = blockIdx.y;
    const int y0 = blockIdx.x * MROWS;
    const int t  = threadIdx.x;
    const int colbase = cs * 128 - 5;
    const float* img = x + bc * PLANE_;

    for (int i = t; i < 138 * 5; i += 128) hist[i] = 0;
    __syncthreads();

    auto addrow = [&](int sy, int sign) {
        int r = sy; if (r < 0) r = -r; else if (r >= HW_) r = 1022 - r;
        const float* row = img + r * HW_;
        for (int xp = t; xp < 138; xp += 128) {
            int sc = colbase + xp;
            int sx = sc < 0 ? -sc : (sc >= HW_ ? 1022 - sc : sc);
            float v = row[sx];
            int q = (int)rintf(v * 15.9375f);
            q = q < 0 ? 0 : (q > 16 ? 16 : q);
            unsigned int inc = 1u << ((q & 3) * 8);
            int addr = xp * 5 + (q >> 2);
            if (sign > 0) hist[addr] += inc; else hist[addr] -= inc;
        }
    };

    for (int sy = y0 - 5; sy < y0 + 5; ++sy) addrow(sy, +1);

    for (int y = y0; y < y0 + MROWS; ++y) {
        addrow(y + 5, +1);
        __syncthreads();
        {
            unsigned int s0 = 0, s1 = 0, s2 = 0, s3 = 0, s4 = 0;
            #pragma unroll
            for (int k = 0; k < 11; ++k) {
                const unsigned int* h = &hist[(t + k) * 5];
                s0 += h[0]; s1 += h[1]; s2 += h[2]; s3 += h[3]; s4 += h[4];
            }
            unsigned int best = s0 & 255u; int bl = 0;
            #define UPD(cnt, l) { unsigned int c_ = (cnt); if (c_ > best) { best = c_; bl = (l); } }
            UPD((s0 >> 8) & 255u, 1)  UPD((s0 >> 16) & 255u, 2)  UPD(s0 >> 24, 3)
            UPD(s1 & 255u, 4) UPD((s1 >> 8) & 255u, 5) UPD((s1 >> 16) & 255u, 6) UPD(s1 >> 24, 7)
            UPD(s2 & 255u, 8) UPD((s2 >> 8) & 255u, 9) UPD((s2 >> 16) & 255u, 10) UPD(s2 >> 24, 11)
            UPD(s3 & 255u, 12) UPD((s3 >> 8) & 255u, 13) UPD((s3 >> 16) & 255u, 14) UPD(s3 >> 24, 15)
            UPD(s4 & 255u, 16)
            #undef UPD
            g_kmode[bc * PLANE_ + y * HW_ + cs * 128 + t] = (unsigned char)bl;
        }
        __syncthreads();
        addrow(y - 5, -1);
    }
}

// ---------------- 2: joint-bin plane + 17^3 histogram -----------------------
__global__ __launch_bounds__(256) void bin_kernel() {
    __shared__ unsigned int sh[NBIN_];
    int t = threadIdx.x;
    for (int i = t; i < NBIN_; i += 256) sh[i] = 0;
    __syncthreads();
    int base = blockIdx.x * 4096;
    #pragma unroll 4
    for (int i = 0; i < 16; ++i) {
        int gp = base + i * 256 + t;
        int b   = gp >> 18;
        int off = gp & (PLANE_ - 1);
        const unsigned char* p = g_kmode + b * 3 * PLANE_ + off;
        int k0 = p[0], k1 = p[PLANE_], k2 = p[2 * PLANE_];
        int bin = k0 + 17 * k1 + 289 * k2;
        g_bin[gp] = (unsigned short)bin;
        atomicAdd(&sh[bin], 1u);
    }
    __syncthreads();
    for (int i = t; i < NBIN_; i += 256) {
        unsigned int v = sh[i];
        if (v) atomicAdd(&g_hist[i], v);
    }
}

// ---------------- 3/4: BN params from the histogram -------------------------
template <int CHAIN>
__global__ __launch_bounds__(256) void stats_kernel(
        const float* __restrict__ w1, const float* __restrict__ b1,
        const float* __restrict__ w2, const float* __restrict__ b2,
        const float* __restrict__ gam, const float* __restrict__ bet,
        const float* __restrict__ w3, const float* __restrict__ b3) {
    int c = blockIdx.x;
    int t = threadIdx.x;
    __shared__ float sw1[18], sb1[6];
    if (t < 18) sw1[t] = w1[t];
    if (t < 6)  sb1[t] = b1[t];
    __syncthreads();
    float wc2[6];
    #pragma unroll
    for (int o = 0; o < 6; ++o) wc2[o] = w2[c * 6 + o];
    float bc2 = b2[c];
    float s1 = 0.f, t1 = 0.f, wc = 0.f, bc = 0.f;
    if (CHAIN) { s1 = g_scale1[c]; t1 = g_bias1[c]; wc = w3[c]; bc = b3[c]; }

    double s = 0.0, ss = 0.0;
    for (int bin = t; bin < NBIN_; bin += 256) {
        unsigned int cnt = g_hist[bin];
        if (!cnt) continue;
        int k2 = bin / 289; int rm = bin - k2 * 289;
        int k1 = rm / 17;   int k0 = rm - k1 * 17;
        float x0 = k0 * 0.0625f, x1 = k1 * 0.0625f, x2 = k2 * 0.0625f;
        float v = bc2;
        #pragma unroll
        for (int o = 0; o < 6; ++o) {
            float m = fmaf(sw1[o*3+2], x2, fmaf(sw1[o*3+1], x1, fmaf(sw1[o*3], x0, sb1[o])));
            v = fmaf(wc2[o], leaky(m), v);
        }
        if (CHAIN) {
            float u = leaky(fmaf(v, s1, t1));
            v = fmaf(u, wc, bc);
        }
        float cf = (float)cnt;
        s  += (double)(cf * v);
        ss += (double)(cf * (v * v));
    }
    __shared__ double rs[256], rq[256];
    rs[t] = s; rq[t] = ss;
    __syncthreads();
    for (int o = 128; o; o >>= 1) {
        if (t < o) { rs[t] += rs[t + o]; rq[t] += rq[t + o]; }
        __syncthreads();
    }
    if (t == 0) {
        const double N = 1048576.0;
        double mean = rs[0] / N;
        double var  = rq[0] / N - mean * mean;
        float sc = gam[c] * (float)(1.0 / sqrt(var + 1e-5));
        if (CHAIN) { g_scale2[c] = sc; g_bias2[c] = bet[c] - (float)mean * sc; }
        else       { g_scale1[c] = sc; g_bias1[c] = bet[c] - (float)mean * sc; }
    }
}

// ---------------- 5: fill h table (bin x 32 channels) ------------------------
__global__ __launch_bounds__(128) void htab_kernel(
        const float* __restrict__ w1, const float* __restrict__ b1,
        const float* __restrict__ w2, const float* __restrict__ b2,
        const float* __restrict__ w3, const float* __restrict__ b3) {
    int bin = blockIdx.x * 128 + threadIdx.x;
    if (bin >= NBIN_) return;
    int k2 = bin / 289; int rm = bin - k2 * 289;
    int k1 = rm / 17;   int k0 = rm - k1 * 17;
    float x0 = k0 * 0.0625f, x1 = k1 * 0.0625f, x2 = k2 * 0.0625f;
    float mid[6];
    #pragma unroll
    for (int o = 0; o < 6; ++o) {
        float m = fmaf(w1[o*3+2], x2, fmaf(w1[o*3+1], x1, fmaf(w1[o*3], x0, b1[o])));
        mid[o] = leaky(m);
    }
    #pragma unroll
    for (int c = 0; c < 32; ++c) {
        float v = b2[c];
        #pragma unroll
        for (int o = 0; o < 6; ++o) v = fmaf(w2[c * 6 + o], mid[o], v);
        float u  = leaky(fmaf(v, g_scale1[c], g_bias1[c]));
        float tt = fmaf(u, w3[c], b3[c]);
        g_htab[bin * 32 + c] = leaky(fmaf(tt, g_scale2[c], g_bias2[c]));
    }
}

// ---------------- 6: level-1 downsample from bin plane + table --------------
// thread = (channel-group of 8) x spatial output; lanes 0-3 cover a full
// 128B table row -> coalesced L2 line per tap.
__global__ __launch_bounds__(256) void down1_kernel(const float* __restrict__ kd) {
    __shared__ float skd[288];
    for (int i = threadIdx.x; i < 288; i += 256) skd[i] = kd[i];
    __syncthreads();
    int gid = blockIdx.x * 256 + threadIdx.x;
    const int TOT = B_ * 171 * 171 * 4;
    if (gid >= TOT) return;
    int cg = gid & 3; int rest = gid >> 2;
    int xo = rest % 171; int r2 = rest / 171;
    int yo = r2 % 171;   int b  = r2 / 171;
    int c0 = cg * 8;
    const unsigned short* binp = g_bin + b * PLANE_;
    float acc[8] = {0.f, 0.f, 0.f, 0.f, 0.f, 0.f, 0.f, 0.f};
    #pragma unroll
    for (int r = 0; r < 3; ++r) {
        int iy = 3 * yo - 1 + r;
        if (iy < 0 || iy >= HW_) continue;
        #pragma unroll
        for (int s = 0; s < 3; ++s) {
            int ix = 3 * xo - 1 + s;
            if (ix < 0 || ix >= HW_) continue;
            int bin = binp[iy * HW_ + ix];
            const float4* hrow = (const float4*)(g_htab + bin * 32 + c0);
            float4 v0 = hrow[0], v1 = hrow[1];
            int kb = r * 3 + s;
            acc[0] = fmaf(skd[(c0+0)*9+kb], v0.x, acc[0]);
            acc[1] = fmaf(skd[(c0+1)*9+kb], v0.y, acc[1]);
            acc[2] = fmaf(skd[(c0+2)*9+kb], v0.z, acc[2]);
            acc[3] = fmaf(skd[(c0+3)*9+kb], v0.w, acc[3]);
            acc[4] = fmaf(skd[(c0+4)*9+kb], v1.x, acc[4]);
            acc[5] = fmaf(skd[(c0+5)*9+kb], v1.y, acc[5]);
            acc[6] = fmaf(skd[(c0+6)*9+kb], v1.z, acc[6]);
            acc[7] = fmaf(skd[(c0+7)*9+kb], v1.w, acc[7]);
        }
    }
    float* outp = g_d1 + ((b * 32 + c0) * 171 + yo) * 171 + xo;
    #pragma unroll
    for (int j = 0; j < 8; ++j) outp[j * 29241] = acc[j];
}

// ---------------- 7: generic pyramid downsample -----------------------------
template <int HIN, int HOUT>
__global__ __launch_bounds__(256) void down_kernel(const float* __restrict__ in,
                                                   float* __restrict__ out,
                                                   const float* __restrict__ kd) {
    int idx = blockIdx.x * 256 + threadIdx.x;
    const int N = B_ * HALF_ * HOUT * HOUT;
    if (idx >= N) return;
    int xo = idx % HOUT; int tmp = idx / HOUT;
    int yo = tmp % HOUT; int pc = tmp / HOUT;
    int c  = pc & 31;
    const float* plane = in + pc * HIN * HIN;
    float acc = 0.f;
    #pragma unroll
    for (int r = 0; r < 3; ++r) {
        int iy = 3 * yo - 1 + r;
        if (iy < 0 || iy >= HIN) continue;
        #pragma unroll
        for (int s = 0; s < 3; ++s) {
            int ix = 3 * xo - 1 + s;
            if (ix < 0 || ix >= HIN) continue;
            acc = fmaf(kd[c * 9 + r * 3 + s], plane[iy * HIN + ix], acc);
        }
    }
    out[idx] = acc;
}

// ---------------- 8: fused pyramid tail d3->d4->d5->d6 (one block) ----------
template <int HIN, int HOUT>
__device__ __forceinline__ void tail_phase(const float* in, float* out,
                                           const float* kd, int t) {
    const int N = B_ * HALF_ * HOUT * HOUT;
    for (int idx = t; idx < N; idx += 1024) {
        int xo = idx % HOUT; int tmp = idx / HOUT;
        int yo = tmp % HOUT; int pc = tmp / HOUT;
        int c  = pc & 31;
        const float* plane = in + pc * HIN * HIN;
        float acc = 0.f;
        #pragma unroll
        for (int r = 0; r < 3; ++r) {
            int iy = 3 * yo - 1 + r;
            if (iy < 0 || iy >= HIN) continue;
            #pragma unroll
            for (int s = 0; s < 3; ++s) {
                int ix = 3 * xo - 1 + s;
                if (ix < 0 || ix >= HIN) continue;
                acc = fmaf(kd[c * 9 + r * 3 + s], plane[iy * HIN + ix], acc);
            }
        }
        out[idx] = acc;
    }
}

__global__ __launch_bounds__(1024) void tail_kernel(const float* __restrict__ kd) {
    int t = threadIdx.x;
    tail_phase<19, 7>(g_d3, g_d4, kd, t); __syncthreads();
    tail_phase<7, 3> (g_d4, g_d5, kd, t); __syncthreads();
    tail_phase<3, 1> (g_d5, g_d6, kd, t);
}

// ---------------- 9: per-level branch coefficients --------------------------
__global__ __launch_bounds__(256) void level_coef_kernel(
        const float* __restrict__ kw, const float* __restrict__ gw, const float* __restrict__ bw,
        const float* __restrict__ kh, const float* __restrict__ gh, const float* __restrict__ bh) {
    int l = blockIdx.y;
    int c = blockIdx.x;
    const float* d; int h;
    switch (l) {
        case 0: d = g_d1; h = 171; break;
        case 1: d = g_d2; h = 57;  break;
        case 2: d = g_d3; h = 19;  break;
        case 3: d = g_d4; h = 7;   break;
        case 4: d = g_d5; h = 3;   break;
        default: d = g_d6; h = 1;  break;
    }
    __shared__ float cnt[171];
    for (int i = threadIdx.x; i < h; i += 256)
        cnt[i] = (float)((512 * (i + 1) + h - 1) / h - (512 * i + h - 1) / h);
    __syncthreads();

    double ws = 0.0, wss = 0.0;
    for (int b = 0; b < 4; ++b)
        for (int i = 0; i < h; ++i) {
            const float* row = d + ((b * 32 + c) * h + i) * h;
            float wi = cnt[i];
            for (int j = threadIdx.x; j < h; j += 256) {
                float v = row[j];
                float w = wi * cnt[j];
                ws  += (double)(w * v);
                wss += (double)w * v * v;
            }
        }
    __shared__ double rs[256], rs2[256];
    rs[threadIdx.x] = ws; rs2[threadIdx.x] = wss;
    __syncthreads();
    for (int o = 128; o; o >>= 1) {
        if (threadIdx.x < o) { rs[threadIdx.x] += rs[threadIdx.x + o]; rs2[threadIdx.x] += rs2[threadIdx.x + o]; }
        __syncthreads();
    }
    if (threadIdx.x == 0) {
        const double N = 1048576.0;
        double mean = rs[0] / N;
        double var  = rs2[0] / N - mean * mean;
        {
            double k = (double)kw[c];
            double inv = 1.0 / sqrt(k * k * var + 1e-5);
            g_cA[l * 64 + c] = (float)(k * gw[c] * inv);
            g_cB[l * 64 + c] = (float)(bw[c] - k * mean * gw[c] * inv);
        }
        {
            double k = (double)kh[c];
            double inv = 1.0 / sqrt(k * k * var + 1e-5);
            g_cA[l * 64 + 32 + c] = (float)(k * gh[c] * inv);
            g_cB[l * 64 + 32 + c] = (float)(bh[c] - k * mean * gh[c] * inv);
        }
    }
}

// ---------------- 10: final gather + sum over 6 levels (4 px/thread) --------
__global__ __launch_bounds__(256) void final_kernel(float* __restrict__ out) {
    __shared__ float sA[384], sB[384];
    for (int i = threadIdx.x; i < 384; i += 256) { sA[i] = g_cA[i]; sB[i] = g_cB[i]; }
    __syncthreads();

    int idx = blockIdx.x * 256 + threadIdx.x;      // 8,388,608 threads
    int x4 = (idx & 127) << 2;
    int y  = (idx >> 7) & 511;
    int ch = (idx >> 16) & 31;
    int b  = idx >> 21;
    float aw[4] = {0.f, 0.f, 0.f, 0.f};
    float ah[4] = {0.f, 0.f, 0.f, 0.f};

    #define LVL(L, HH, PTR) { \
        int ri = (y * HH) >> 9; \
        const float* rowp = PTR + ((b * 32 + ch) * HH + ri) * HH; \
        float A0 = sA[(L)*64+ch], B0 = sB[(L)*64+ch]; \
        float A1 = sA[(L)*64+32+ch], B1 = sB[(L)*64+32+ch]; \
        _Pragma("unroll") \
        for (int p = 0; p < 4; ++p) { \
            int ci = ((x4 + p) * HH) >> 9; \
            float dv = rowp[ci]; \
            float tw = fmaf(dv, A0, B0); aw[p] += fmaxf(tw, 0.01f * tw); \
            float th = fmaf(dv, A1, B1); ah[p] += fmaxf(th, 0.01f * th); } }

    LVL(0, 171, g_d1)
    LVL(1, 57,  g_d2)
    LVL(2, 19,  g_d3)
    LVL(3, 7,   g_d4)
    LVL(4, 3,   g_d5)
    LVL(5, 1,   g_d6)
    #undef LVL

    int ob = ((b * 64 + ch) << 18) + (y << 9) + x4;
    *(float4*)(out + ob) = make_float4(aw[0], aw[1], aw[2], aw[3]);
    *(float4*)(out + ob + (32 << 18)) = make_float4(ah[0], ah[1], ah[2], ah[3]);
}

// ---------------- launch ----------------------------------------------------
extern "C" void kernel_launch(void* const* d_in, const int* in_sizes, int n_in,
                              void* d_out, int out_size) {
    const float* x    = (const float*)d_in[0];
    const float* w1   = (const float*)d_in[1];
    const float* b1   = (const float*)d_in[2];
    const float* w2   = (const float*)d_in[3];
    const float* b2   = (const float*)d_in[4];
    const float* bn1g = (const float*)d_in[5];
    const float* bn1b = (const float*)d_in[6];
    const float* w3   = (const float*)d_in[7];
    const float* b3   = (const float*)d_in[8];
    const float* bn2g = (const float*)d_in[9];
    const float* bn2b = (const float*)d_in[10];
    const float* kd   = (const float*)d_in[11];
    const float* kw   = (const float*)d_in[12];
    const float* bwg  = (const float*)d_in[13];
    const float* bwb  = (const float*)d_in[14];
    const float* kh   = (const float*)d_in[15];
    const float* bhg  = (const float*)d_in[16];
    const float* bhb  = (const float*)d_in[17];
    float* out = (float*)d_out;

    zero_hist_kernel<<<1, 1024>>>();
    mode_kernel<<<dim3(64, 4, 12), 128>>>(x);
    bin_kernel<<<256, 256>>>();
    stats_kernel<0><<<32, 256>>>(w1, b1, w2, b2, bn1g, bn1b, w3, b3);
    stats_kernel<1><<<32, 256>>>(w1, b1, w2, b2, bn2g, bn2b, w3, b3);
    htab_kernel<<<(NBIN_ + 127) / 128, 128>>>(w1, b1, w2, b2, w3, b3);
    down1_kernel<<<(B_ * 171 * 171 * 4 + 255) / 256, 256>>>(kd);

    { float *p1, *p2, *p3;
      cudaGetSymbolAddress((void**)&p1, g_d1);
      cudaGetSymbolAddress((void**)&p2, g_d2);
      cudaGetSymbolAddress((void**)&p3, g_d3);
      down_kernel<171, 57><<<(B_ * HALF_ * 57 * 57 + 255) / 256, 256>>>(p1, p2, kd);
      down_kernel<57, 19> <<<(B_ * HALF_ * 19 * 19 + 255) / 256, 256>>>(p2, p3, kd);
    }
    tail_kernel<<<1, 1024>>>(kd);

    level_coef_kernel<<<dim3(32, 6), 256>>>(kw, bwg, bwb, kh, bhg, bhb);
    final_kernel<<<32768, 256>>>(out);
}

// round 5
// speedup vs baseline: 1.3779x; 1.3779x over previous
#include <cuda_runtime.h>
#include <math.h>

#define B_    4
#define HW_   512
#define PLANE_ 262144
#define NBIN_ 4913
#define NPIXD 1048576.0

__device__ __align__(128) unsigned char  g_kmode[12 * PLANE_];
__device__ __align__(128) unsigned short g_bin[4 * PLANE_];
__device__ unsigned int g_hist[NBIN_];              // zero-init; re-zeroed in params_kernel
__device__ __align__(128) float g_htab[NBIN_ * 32]; // pre-BN2 "tt"
__device__ float g_d1[4 * 32 * 171 * 171];
__device__ float g_d2[4 * 32 * 57 * 57];
__device__ float g_d3[4 * 32 * 19 * 19];
__device__ float g_d4[4 * 32 * 7 * 7];
__device__ float g_d5[4 * 32 * 3 * 3];
__device__ float g_d6[4 * 32];
__device__ float g_scale2[32], g_bias2[32];
__device__ double g_lvS[96], g_lvQ[96];             // levels 0..2 weighted stats
__device__ float g_cA[384], g_cB[384];

__device__ __forceinline__ float leaky(float v) { return fmaxf(v, 0.01f * v); }

template <int H>
__device__ __forceinline__ int upcnt(int i) {
    return (512 * (i + 1) + H - 1) / H - (512 * i + H - 1) / H;
}

// ---------------- 1: mode pooling ------------------------------------------
#define MROWS 8
__global__ __launch_bounds__(128) void mode_kernel(const float* __restrict__ x) {
    __shared__ unsigned int hist[138 * 5];
    const int bc = blockIdx.z, cs = blockIdx.y;
    const int y0 = blockIdx.x * MROWS;
    const int t  = threadIdx.x;
    const int colbase = cs * 128 - 5;
    const float* img = x + bc * PLANE_;

    for (int i = t; i < 138 * 5; i += 128) hist[i] = 0;
    __syncthreads();

    auto addrow = [&](int sy, int sign) {
        int r = sy; if (r < 0) r = -r; else if (r >= HW_) r = 1022 - r;
        const float* row = img + r * HW_;
        for (int xp = t; xp < 138; xp += 128) {
            int sc = colbase + xp;
            int sx = sc < 0 ? -sc : (sc >= HW_ ? 1022 - sc : sc);
            int q = __float2int_rn(row[sx] * 15.9375f);
            q = q < 0 ? 0 : (q > 16 ? 16 : q);
            unsigned int inc = 1u << ((q & 3) * 8);
            int addr = xp * 5 + (q >> 2);
            if (sign > 0) hist[addr] += inc; else hist[addr] -= inc;
        }
    };

    for (int sy = y0 - 5; sy < y0 + 5; ++sy) addrow(sy, +1);

    for (int y = y0; y < y0 + MROWS; ++y) {
        addrow(y + 5, +1);
        __syncthreads();
        {
            unsigned int s0 = 0, s1 = 0, s2 = 0, s3 = 0, s4 = 0;
            #pragma unroll
            for (int k = 0; k < 11; ++k) {
                const unsigned int* h = &hist[(t + k) * 5];
                s0 += h[0]; s1 += h[1]; s2 += h[2]; s3 += h[3]; s4 += h[4];
            }
            unsigned int best = s0 & 255u; int bl = 0;
            #define UPD(cnt, l) { unsigned int c_ = (cnt); if (c_ > best) { best = c_; bl = (l); } }
            UPD((s0 >> 8) & 255u, 1)  UPD((s0 >> 16) & 255u, 2)  UPD(s0 >> 24, 3)
            UPD(s1 & 255u, 4) UPD((s1 >> 8) & 255u, 5) UPD((s1 >> 16) & 255u, 6) UPD(s1 >> 24, 7)
            UPD(s2 & 255u, 8) UPD((s2 >> 8) & 255u, 9) UPD((s2 >> 16) & 255u, 10) UPD(s2 >> 24, 11)
            UPD(s3 & 255u, 12) UPD((s3 >> 8) & 255u, 13) UPD((s3 >> 16) & 255u, 14) UPD(s3 >> 24, 15)
            UPD(s4 & 255u, 16)
            #undef UPD
            g_kmode[bc * PLANE_ + y * HW_ + cs * 128 + t] = (unsigned char)bl;
        }
        __syncthreads();
        addrow(y - 5, -1);
    }
}

// ---------------- 2: joint-bin plane + 17^3 histogram -----------------------
__global__ __launch_bounds__(256) void bin_kernel() {
    __shared__ unsigned int sh[NBIN_];
    int t = threadIdx.x;
    for (int i = t; i < NBIN_; i += 256) sh[i] = 0;
    __syncthreads();
    int base = blockIdx.x * 4096;
    #pragma unroll 4
    for (int i = 0; i < 16; ++i) {
        int gp = base + i * 256 + t;
        int b = gp >> 18, off = gp & (PLANE_ - 1);
        const unsigned char* p = g_kmode + b * 3 * PLANE_ + off;
        int bin = p[0] + 17 * p[PLANE_] + 289 * p[2 * PLANE_];
        g_bin[gp] = (unsigned short)bin;
        atomicAdd(&sh[bin], 1u);
    }
    __syncthreads();
    for (int i = t; i < NBIN_; i += 256) {
        unsigned int v = sh[i];
        if (v) atomicAdd(&g_hist[i], v);
    }
}

// ---------------- 3: BN1 + BN2 params + htab, one block ---------------------
__global__ __launch_bounds__(1024) void params_kernel(
        const float* __restrict__ w1, const float* __restrict__ b1,
        const float* __restrict__ w2, const float* __restrict__ b2,
        const float* __restrict__ g1, const float* __restrict__ be1,
        const float* __restrict__ w3, const float* __restrict__ b3,
        const float* __restrict__ g2, const float* __restrict__ be2) {
    __shared__ float sw1[18], sb1[6], ss1[32], st1[32];
    __shared__ double rs[32][33], rq[32][33];
    int t = threadIdx.x;
    if (t < 18) sw1[t] = w1[t];
    if (t < 6)  sb1[t] = b1[t];
    __syncthreads();

    int c = t & 31, g = t >> 5;
    float w2c[6];
    #pragma unroll
    for (int o = 0; o < 6; ++o) w2c[o] = w2[c * 6 + o];
    float bc2 = b2[c];

    // pass A: BN1 stats
    double s = 0.0, q = 0.0;
    for (int bin = g; bin < NBIN_; bin += 32) {
        unsigned int cnt = g_hist[bin];
        if (!cnt) continue;
        int k2 = bin / 289, rm = bin - 289 * k2, k1 = rm / 17, k0 = rm - 17 * k1;
        float x0 = k0 * 0.0625f, x1 = k1 * 0.0625f, x2 = k2 * 0.0625f;
        float v = bc2;
        #pragma unroll
        for (int o = 0; o < 6; ++o) {
            float m = fmaf(sw1[o*3+2], x2, fmaf(sw1[o*3+1], x1, fmaf(sw1[o*3], x0, sb1[o])));
            v = fmaf(w2c[o], leaky(m), v);
        }
        float cf = (float)cnt;
        s += (double)(cf * v); q += (double)(cf * (v * v));
    }
    rs[g][c] = s; rq[g][c] = q;
    __syncthreads();
    if (t < 32) {
        double S = 0.0, Q = 0.0;
        for (int j = 0; j < 32; ++j) { S += rs[j][t]; Q += rq[j][t]; }
        double mean = S / NPIXD, var = Q / NPIXD - mean * mean;
        float sc = g1[t] * (float)(1.0 / sqrt(var + 1e-5));
        ss1[t] = sc; st1[t] = be1[t] - (float)mean * sc;
    }
    __syncthreads();

    // pass B: chained BN2 stats + htab store
    float s1 = ss1[c], t1 = st1[c], w3c = w3[c], b3c = b3[c];
    s = 0.0; q = 0.0;
    for (int bin = g; bin < NBIN_; bin += 32) {
        int k2 = bin / 289, rm = bin - 289 * k2, k1 = rm / 17, k0 = rm - 17 * k1;
        float x0 = k0 * 0.0625f, x1 = k1 * 0.0625f, x2 = k2 * 0.0625f;
        float v = bc2;
        #pragma unroll
        for (int o = 0; o < 6; ++o) {
            float m = fmaf(sw1[o*3+2], x2, fmaf(sw1[o*3+1], x1, fmaf(sw1[o*3], x0, sb1[o])));
            v = fmaf(w2c[o], leaky(m), v);
        }
        float u  = leaky(fmaf(v, s1, t1));
        float tt = fmaf(u, w3c, b3c);
        g_htab[bin * 32 + c] = tt;
        float cf = (float)g_hist[bin];
        s += (double)(cf * tt); q += (double)(cf * (tt * tt));
    }
    __syncthreads();
    rs[g][c] = s; rq[g][c] = q;
    __syncthreads();
    if (t < 32) {
        double S = 0.0, Q = 0.0;
        for (int j = 0; j < 32; ++j) { S += rs[j][t]; Q += rq[j][t]; }
        double mean = S / NPIXD, var = Q / NPIXD - mean * mean;
        float sc = g2[t] * (float)(1.0 / sqrt(var + 1e-5));
        g_scale2[t] = sc; g_bias2[t] = be2[t] - (float)mean * sc;
    }
    // cleanup for graph replay + zero level accumulators
    for (int i = t; i < NBIN_; i += 1024) g_hist[i] = 0u;
    if (t < 96) { g_lvS[t] = 0.0; g_lvQ[t] = 0.0; }
}

// ---------------- 4: level-1 downsample + fused level-0 stats ---------------
__global__ __launch_bounds__(256) void down1_kernel(const float* __restrict__ kd) {
    __shared__ float skd[288], bs[32], bq[32];
    int t = threadIdx.x;
    for (int i = t; i < 288; i += 256) skd[i] = kd[i];
    if (t < 32) { bs[t] = 0.f; bq[t] = 0.f; }
    __syncthreads();

    int gid = blockIdx.x * 256 + t;
    const int TOT = B_ * 171 * 171 * 4;
    bool valid = gid < TOT;
    int gg = valid ? gid : 0;
    int cg = gg & 3; int rest = gg >> 2;
    int xo = rest % 171; int r2 = rest / 171;
    int yo = r2 % 171;   int b  = r2 / 171;
    int c0 = cg * 8;

    float s2[8], t2[8];
    #pragma unroll
    for (int j = 0; j < 8; ++j) { s2[j] = g_scale2[c0 + j]; t2[j] = g_bias2[c0 + j]; }

    float acc[8] = {0.f,0.f,0.f,0.f,0.f,0.f,0.f,0.f};
    if (valid) {
        const unsigned short* binp = g_bin + b * PLANE_;
        #pragma unroll
        for (int r = 0; r < 3; ++r) {
            int iy = 3 * yo - 1 + r;
            if (iy < 0 || iy >= HW_) continue;
            #pragma unroll
            for (int sx = 0; sx < 3; ++sx) {
                int ix = 3 * xo - 1 + sx;
                if (ix < 0 || ix >= HW_) continue;
                int bin = binp[iy * HW_ + ix];
                const float4* hrow = (const float4*)(g_htab + bin * 32 + c0);
                float4 v0 = hrow[0], v1 = hrow[1];
                float hv[8] = {v0.x,v0.y,v0.z,v0.w,v1.x,v1.y,v1.z,v1.w};
                int kb = r * 3 + sx;
                #pragma unroll
                for (int j = 0; j < 8; ++j) {
                    float h = leaky(fmaf(hv[j], s2[j], t2[j]));
                    acc[j] = fmaf(skd[(c0 + j) * 9 + kb], h, acc[j]);
                }
            }
        }
        float* outp = g_d1 + ((b * 32 + c0) * 171 + yo) * 171 + xo;
        #pragma unroll
        for (int j = 0; j < 8; ++j) outp[j * 29241] = acc[j];
    }
    float w = valid ? (float)(upcnt<171>(yo) * upcnt<171>(xo)) : 0.f;
    float pv[16];
    #pragma unroll
    for (int j = 0; j < 8; ++j) { pv[j] = w * acc[j]; pv[8 + j] = w * acc[j] * acc[j]; }
    #pragma unroll
    for (int off = 4; off < 32; off <<= 1)
        #pragma unroll
        for (int k = 0; k < 16; ++k) pv[k] += __shfl_xor_sync(0xFFFFFFFFu, pv[k], off);
    int lane = t & 31;
    if (lane < 4) {
        int cc = lane * 8;
        #pragma unroll
        for (int j = 0; j < 8; ++j) {
            atomicAdd(&bs[cc + j], pv[j]);
            atomicAdd(&bq[cc + j], pv[8 + j]);
        }
    }
    __syncthreads();
    if (t < 32) {
        if (bs[t] != 0.f) atomicAdd(&g_lvS[t], (double)bs[t]);
        if (bq[t] != 0.f) atomicAdd(&g_lvQ[t], (double)bq[t]);
    }
}

// ---------------- 5: pyramid downsample + fused level stats -----------------
template <int HIN, int HOUT, int LVL>
__global__ __launch_bounds__(256) void down_kernel(const float* __restrict__ in,
                                                   float* __restrict__ out,
                                                   const float* __restrict__ kd) {
    __shared__ float bs[32], bq[32];
    int t = threadIdx.x;
    if (t < 32) { bs[t] = 0.f; bq[t] = 0.f; }
    __syncthreads();
    int idx = blockIdx.x * 256 + t;
    const int N = B_ * 32 * HOUT * HOUT;
    if (idx < N) {
        int xo = idx % HOUT; int tmp = idx / HOUT;
        int yo = tmp % HOUT; int pc = tmp / HOUT;
        int c  = pc & 31;
        const float* plane = in + pc * HIN * HIN;
        float acc = 0.f;
        #pragma unroll
        for (int r = 0; r < 3; ++r) {
            int iy = 3 * yo - 1 + r;
            if (iy < 0 || iy >= HIN) continue;
            #pragma unroll
            for (int sx = 0; sx < 3; ++sx) {
                int ix = 3 * xo - 1 + sx;
                if (ix < 0 || ix >= HIN) continue;
                acc = fmaf(kd[c * 9 + r * 3 + sx], plane[iy * HIN + ix], acc);
            }
        }
        out[idx] = acc;
        float w = (float)(upcnt<HOUT>(yo) * upcnt<HOUT>(xo));
        atomicAdd(&bs[c], w * acc);
        atomicAdd(&bq[c], w * acc * acc);
    }
    __syncthreads();
    if (t < 32) {
        if (bs[t] != 0.f) atomicAdd(&g_lvS[LVL * 32 + t], (double)bs[t]);
        if (bq[t] != 0.f) atomicAdd(&g_lvQ[LVL * 32 + t], (double)bq[t]);
    }
}

// ---------------- 6: tail d3->d4->d5->d6 + stats lvl3..5 + coef finalize ----
template <int HIN, int HOUT>
__device__ __forceinline__ void tail_phase(const float* in, float* out,
                                           const float* kd, int t) {
    const int N = B_ * 32 * HOUT * HOUT;
    for (int idx = t; idx < N; idx += 1024) {
        int xo = idx % HOUT; int tmp = idx / HOUT;
        int yo = tmp % HOUT; int pc = tmp / HOUT;
        int c  = pc & 31;
        const float* plane = in + pc * HIN * HIN;
        float acc = 0.f;
        #pragma unroll
        for (int r = 0; r < 3; ++r) {
            int iy = 3 * yo - 1 + r;
            if (iy < 0 || iy >= HIN) continue;
            #pragma unroll
            for (int sx = 0; sx < 3; ++sx) {
                int ix = 3 * xo - 1 + sx;
                if (ix < 0 || ix >= HIN) continue;
                acc = fmaf(kd[c * 9 + r * 3 + sx], plane[iy * HIN + ix], acc);
            }
        }
        out[idx] = acc;
    }
}

template <int H, int LVL>
__device__ __forceinline__ void tail_stats(const float* d, double* sS, double* sQ, int t) {
    int wid = t >> 5, lane = t & 31;   // warp = channel
    const int PER = B_ * H * H;
    float fs = 0.f, fq = 0.f;
    for (int j = lane; j < PER; j += 32) {
        int b = j / (H * H); int p = j - b * H * H;
        int yo = p / H, xo = p - yo * H;
        float v = d[(b * 32 + wid) * H * H + p];
        float w = (float)(upcnt<H>(yo) * upcnt<H>(xo));
        fs = fmaf(w, v, fs);
        fq = fmaf(w, v * v, fq);
    }
    #pragma unroll
    for (int r = 16; r; r >>= 1) {
        fs += __shfl_down_sync(0xFFFFFFFFu, fs, r);
        fq += __shfl_down_sync(0xFFFFFFFFu, fq, r);
    }
    if (lane == 0) { sS[LVL * 32 + wid] = (double)fs; sQ[LVL * 32 + wid] = (double)fq; }
}

__global__ __launch_bounds__(1024) void tail_kernel(
        const float* __restrict__ kd,
        const float* __restrict__ kw, const float* __restrict__ gw, const float* __restrict__ bw,
        const float* __restrict__ kh, const float* __restrict__ gh, const float* __restrict__ bh) {
    __shared__ double sS[192], sQ[192];
    int t = threadIdx.x;
    tail_phase<19, 7>(g_d3, g_d4, kd, t); __syncthreads();
    tail_phase<7, 3> (g_d4, g_d5, kd, t); __syncthreads();
    tail_phase<3, 1> (g_d5, g_d6, kd, t); __syncthreads();
    tail_stats<7, 3>(g_d4, sS, sQ, t);
    tail_stats<3, 4>(g_d5, sS, sQ, t);
    tail_stats<1, 5>(g_d6, sS, sQ, t);
    __syncthreads();
    if (t < 192) {
        int l = t >> 5, c = t & 31;
        double S = (l < 3) ? g_lvS[t] : sS[t];
        double Q = (l < 3) ? g_lvQ[t] : sQ[t];
        double mean = S / NPIXD;
        double var  = Q / NPIXD - mean * mean;
        double k = (double)kw[c];
        double inv = 1.0 / sqrt(k * k * var + 1e-5);
        g_cA[l * 64 + c] = (float)(k * gw[c] * inv);
        g_cB[l * 64 + c] = (float)(bw[c] - k * mean * gw[c] * inv);
        k = (double)kh[c];
        inv = 1.0 / sqrt(k * k * var + 1e-5);
        g_cA[l * 64 + 32 + c] = (float)(k * gh[c] * inv);
        g_cB[l * 64 + 32 + c] = (float)(bh[c] - k * mean * gh[c] * inv);
    }
}

// ---------------- 7: final gather + sum over 6 levels (4 px/thread) ---------
__global__ __launch_bounds__(256) void final_kernel(float* __restrict__ out) {
    __shared__ float sA[384], sB[384];
    for (int i = threadIdx.x; i < 384; i += 256) { sA[i] = g_cA[i]; sB[i] = g_cB[i]; }
    __syncthreads();

    int idx = blockIdx.x * 256 + threadIdx.x;
    int x4 = (idx & 127) << 2;
    int y  = (idx >> 7) & 511;
    int ch = (idx >> 16) & 31;
    int b  = idx >> 21;
    float aw[4] = {0.f,0.f,0.f,0.f};
    float ah[4] = {0.f,0.f,0.f,0.f};

    #define LVL(L, HH, PTR) { \
        int ri = (y * HH) >> 9; \
        const float* rowp = PTR + ((b * 32 + ch) * HH + ri) * HH; \
        float A0 = sA[(L)*64+ch], B0 = sB[(L)*64+ch]; \
        float A1 = sA[(L)*64+32+ch], B1 = sB[(L)*64+32+ch]; \
        _Pragma("unroll") \
        for (int p = 0; p < 4; ++p) { \
            int ci = ((x4 + p) * HH) >> 9; \
            float dv = rowp[ci]; \
            float tw = fmaf(dv, A0, B0); aw[p] += fmaxf(tw, 0.01f * tw); \
            float th = fmaf(dv, A1, B1); ah[p] += fmaxf(th, 0.01f * th); } }

    LVL(0, 171, g_d1)
    LVL(1, 57,  g_d2)
    LVL(2, 19,  g_d3)
    LVL(3, 7,   g_d4)
    LVL(4, 3,   g_d5)
    LVL(5, 1,   g_d6)
    #undef LVL

    int ob = ((b * 64 + ch) << 18) + (y << 9) + x4;
    *(float4*)(out + ob) = make_float4(aw[0], aw[1], aw[2], aw[3]);
    *(float4*)(out + ob + (32 << 18)) = make_float4(ah[0], ah[1], ah[2], ah[3]);
}

// ---------------- launch ----------------------------------------------------
extern "C" void kernel_launch(void* const* d_in, const int* in_sizes, int n_in,
                              void* d_out, int out_size) {
    const float* x    = (const float*)d_in[0];
    const float* w1   = (const float*)d_in[1];
    const float* b1   = (const float*)d_in[2];
    const float* w2   = (const float*)d_in[3];
    const float* b2   = (const float*)d_in[4];
    const float* bn1g = (const float*)d_in[5];
    const float* bn1b = (const float*)d_in[6];
    const float* w3   = (const float*)d_in[7];
    const float* b3   = (const float*)d_in[8];
    const float* bn2g = (const float*)d_in[9];
    const float* bn2b = (const float*)d_in[10];
    const float* kd   = (const float*)d_in[11];
    const float* kw   = (const float*)d_in[12];
    const float* bwg  = (const float*)d_in[13];
    const float* bwb  = (const float*)d_in[14];
    const float* kh   = (const float*)d_in[15];
    const float* bhg  = (const float*)d_in[16];
    const float* bhb  = (const float*)d_in[17];
    float* out = (float*)d_out;

    mode_kernel<<<dim3(64, 4, 12), 128>>>(x);
    bin_kernel<<<256, 256>>>();
    params_kernel<<<1, 1024>>>(w1, b1, w2, b2, bn1g, bn1b, w3, b3, bn2g, bn2b);
    down1_kernel<<<(B_ * 171 * 171 * 4 + 255) / 256, 256>>>(kd);

    { float *p1, *p2, *p3;
      cudaGetSymbolAddress((void**)&p1, g_d1);
      cudaGetSymbolAddress((void**)&p2, g_d2);
      cudaGetSymbolAddress((void**)&p3, g_d3);
      down_kernel<171, 57, 1><<<(B_ * 32 * 57 * 57 + 255) / 256, 256>>>(p1, p2, kd);
      down_kernel<57, 19, 2> <<<(B_ * 32 * 19 * 19 + 255) / 256, 256>>>(p2, p3, kd);
    }
    tail_kernel<<<1, 1024>>>(kd, kw, bwg, bwb, kh, bhg, bhb);
    final_kernel<<<32768, 256>>>(out);
}